// round 1
// baseline (speedup 1.0000x reference)
#include <cuda_runtime.h>
#include <math.h>

#define DD 256   // feature dim D
#define SS 8     // memory slots S

// Precomputed keyV + state_bias, loop-invariant. __device__ global = legal scratch.
__device__ float g_kvb[SS * DD];

// ---------------------------------------------------------------------------
// Prologue: kvb[s][e] = sum_d keys[s][d] * V[d][e] + state_bias[e]
// ---------------------------------------------------------------------------
__global__ void kvb_kernel(const float* __restrict__ keys,
                           const float* __restrict__ V,
                           const float* __restrict__ state_bias) {
    const int s = blockIdx.x;
    const int e = threadIdx.x;
    __shared__ float krow[DD];
    krow[e] = keys[s * DD + e];
    __syncthreads();
    float acc = state_bias[e];
#pragma unroll 4
    for (int d = 0; d < DD; ++d)
        acc = fmaf(krow[d], V[d * DD + e], acc);
    g_kvb[s * DD + e] = acc;
}

// ---------------------------------------------------------------------------
// Main recurrent kernel: one CTA per batch element, runs exactly lengths[b]
// steps (mask == loop bound, so finished batches cost nothing).
// SMEM state is stored transposed st[d][s] so the GEMM inner loop reads one
// broadcast LDS.128 pair per d.
// ---------------------------------------------------------------------------
__global__ __launch_bounds__(256, 4) void dm_kernel(
    const float* __restrict__ inputs,   // [B, T, D]
    const int*   __restrict__ lengths,  // [B]
    const float* __restrict__ keys,     // [S, D]
    const float* __restrict__ U,        // [D, D]
    const float* __restrict__ W,        // [D, D]
    const float* __restrict__ gate_bias,// [1]
    float*       __restrict__ out,      // [B, S, D]
    int T)
{
    const int b    = blockIdx.x;
    const int e    = threadIdx.x;       // output column owned by this thread
    const int lane = e & 31;
    const int warp = e >> 5;

    __shared__ __align__(16) float st[DD][SS];   // states transposed [d][s]
    __shared__ __align__(16) float kT[DD][SS];   // keys transposed
    __shared__ float kvb[SS * DD];               // keyV + state_bias
    __shared__ float xs[DD];                     // current x
    __shared__ float red1[8][SS];                // gate-logit partials per warp
    __shared__ float red2[8][SS];                // norm partials per warp

#pragma unroll
    for (int s = 0; s < SS; ++s) {
        float k = keys[s * DD + e];
        kT[e][s] = k;
        st[e][s] = k;                 // init_states = keys broadcast
        kvb[s * DD + e] = g_kvb[s * DD + e];
    }

    const int   len   = lengths[b];
    const float gbias = gate_bias[0];
    const float* xbase = inputs + (size_t)b * T * DD + e;
    const float* Up    = U + e;
    const float* Wp    = W + e;

    for (int t = 0; t < len; ++t) {
        __syncthreads();              // S_a: prev-iter st writes / xs reads done
        const float xv = xbase[(size_t)t * DD];
        xs[e] = xv;
        __syncthreads();              // S_b: xs visible

        // ---- gate logits: <x, st_s + key_s> (fused: g uses x.st + x.key) ----
        float p[SS];
#pragma unroll
        for (int s = 0; s < SS; ++s)
            p[s] = xv * (st[e][s] + kT[e][s]);
#pragma unroll
        for (int s = 0; s < SS; ++s) {
#pragma unroll
            for (int o = 16; o > 0; o >>= 1)
                p[s] += __shfl_xor_sync(0xffffffffu, p[s], o);
        }
        if (lane == 0) {
#pragma unroll
            for (int s = 0; s < SS; ++s) red1[warp][s] = p[s];
        }

        // ---- GEMM: acc[s] = sum_d st[s][d]*U[d][e];  xw = sum_d x[d]*W[d][e]
        float acc0 = 0.f, acc1 = 0.f, acc2 = 0.f, acc3 = 0.f;
        float acc4 = 0.f, acc5 = 0.f, acc6 = 0.f, acc7 = 0.f;
        float xw = 0.f;
#pragma unroll 4
        for (int d = 0; d < DD; ++d) {
            const float u = Up[d * DD];
            const float w = Wp[d * DD];
            const float4 a = *(const float4*)&st[d][0];
            const float4 c = *(const float4*)&st[d][4];
            acc0 = fmaf(a.x, u, acc0);
            acc1 = fmaf(a.y, u, acc1);
            acc2 = fmaf(a.z, u, acc2);
            acc3 = fmaf(a.w, u, acc3);
            acc4 = fmaf(c.x, u, acc4);
            acc5 = fmaf(c.y, u, acc5);
            acc6 = fmaf(c.z, u, acc6);
            acc7 = fmaf(c.w, u, acc7);
            xw   = fmaf(xs[d], w, xw);
        }
        __syncthreads();              // S_c: red1 complete, GEMM st reads done

        // ---- gates (redundant per-thread finalize: avoids a sync) ----
        float g[SS];
#pragma unroll
        for (int s = 0; s < SS; ++s) {
            float v = gbias;
#pragma unroll
            for (int w2 = 0; w2 < 8; ++w2) v += red1[w2][s];
            g[s] = 1.f / (1.f + expf(-v));
        }

        // ---- h = st + g * elu(acc + kvb + xw);  norm partials ----
        float acc[SS] = {acc0, acc1, acc2, acc3, acc4, acc5, acc6, acc7};
        float h[SS], q[SS];
#pragma unroll
        for (int s = 0; s < SS; ++s) {
            float pre = acc[s] + kvb[s * DD + e] + xw;
            float ht  = pre > 0.f ? pre : expm1f(pre);
            h[s] = st[e][s] + g[s] * ht;
            q[s] = h[s] * h[s];
        }
#pragma unroll
        for (int s = 0; s < SS; ++s) {
#pragma unroll
            for (int o = 16; o > 0; o >>= 1)
                q[s] += __shfl_xor_sync(0xffffffffu, q[s], o);
        }
        if (lane == 0) {
#pragma unroll
            for (int s = 0; s < SS; ++s) red2[warp][s] = q[s];
        }
        __syncthreads();              // S_d: red2 complete, combine st reads done

        // ---- normalize and write back states ----
#pragma unroll
        for (int s = 0; s < SS; ++s) {
            float n2 = 0.f;
#pragma unroll
            for (int w2 = 0; w2 < 8; ++w2) n2 += red2[w2][s];
            // 1/max(sqrt(n2), 1e-12): equal to rsqrt when n2 > 1e-24
            float r = (n2 > 1e-24f) ? rsqrtf(n2) : 1e12f;
            st[e][s] = h[s] * r;
        }
    }

    __syncthreads();
    float* ob = out + (size_t)b * SS * DD;
#pragma unroll
    for (int s = 0; s < SS; ++s)
        ob[s * DD + e] = st[e][s];
}

// ---------------------------------------------------------------------------
// Harness entry. Input order (metadata): inputs, lengths, keys, U, V, W,
// gate_bias, state_bias. Output: final states [B, S, D] fp32.
// ---------------------------------------------------------------------------
extern "C" void kernel_launch(void* const* d_in, const int* in_sizes, int n_in,
                              void* d_out, int out_size) {
    const float* inputs     = (const float*)d_in[0];
    const int*   lengths    = (const int*)  d_in[1];
    const float* keys       = (const float*)d_in[2];
    const float* U          = (const float*)d_in[3];
    const float* V          = (const float*)d_in[4];
    const float* W          = (const float*)d_in[5];
    const float* gate_bias  = (const float*)d_in[6];
    const float* state_bias = (const float*)d_in[7];

    const int B = in_sizes[1];                 // lengths element count
    const int T = in_sizes[0] / (B * DD);      // inputs = B*T*D

    kvb_kernel<<<SS, DD>>>(keys, V, state_bias);
    dm_kernel<<<B, DD>>>(inputs, lengths, keys, U, W, gate_bias,
                         (float*)d_out, T);
}

// round 2
// speedup vs baseline: 1.3164x; 1.3164x over previous
#include <cuda_runtime.h>
#include <math.h>

#define DD 256   // feature dim D
#define SS 8     // memory slots S
#define MAXB 512
#define MAXT 256
#define TM 32    // rows per XW tile

// Legal scratch: __device__ globals.
__device__ float g_kvb[SS * DD];                         // keys@V + state_bias
__device__ float g_xw[(size_t)MAXB * MAXT * DD];         // x@W     [B,T,D] (134MB)
__device__ float g_gk[(size_t)MAXB * MAXT * SS];         // x@keys^T[B,T,S] (4MB)

// ---------------------------------------------------------------------------
// kvb[s][e] = sum_d keys[s][d] * V[d][e] + state_bias[e]
// ---------------------------------------------------------------------------
__global__ void kvb_kernel(const float* __restrict__ keys,
                           const float* __restrict__ V,
                           const float* __restrict__ state_bias) {
    const int s = blockIdx.x;
    const int e = threadIdx.x;
    __shared__ float krow[DD];
    krow[e] = keys[s * DD + e];
    __syncthreads();
    float acc = state_bias[e];
#pragma unroll 4
    for (int d = 0; d < DD; ++d)
        acc = fmaf(krow[d], V[(size_t)d * DD + e], acc);
    g_kvb[s * DD + e] = acc;
}

// ---------------------------------------------------------------------------
// Precompute XW[b,t,:] = x@W and GK[b,t,:] = x@keys^T for t < len[b].
// One block per (t-tile of 32 rows, batch). A-tile staged transposed in SMEM.
// ---------------------------------------------------------------------------
__global__ __launch_bounds__(256) void xw_kernel(
    const float* __restrict__ inputs,   // [B,T,D]
    const int*   __restrict__ lengths,
    const float* __restrict__ W,        // [D,D]
    const float* __restrict__ keys,     // [S,D]
    int T)
{
    const int b  = blockIdx.y;
    const int t0 = blockIdx.x * TM;
    if (t0 >= lengths[b]) return;        // fully-masked tile: no work
    const int rows = min(TM, T - t0);

    __shared__ __align__(16) float As[DD][TM];   // transposed x-tile, 32KB
    const float* A = inputs + ((size_t)b * T + t0) * DD;
    const int tid = threadIdx.x;

    for (int i = tid; i < rows * (DD / 4); i += 256) {
        const int m = i / (DD / 4), d4 = i % (DD / 4);
        const float4 v = *(const float4*)&A[(size_t)m * DD + d4 * 4];
        As[d4 * 4 + 0][m] = v.x;
        As[d4 * 4 + 1][m] = v.y;
        As[d4 * 4 + 2][m] = v.z;
        As[d4 * 4 + 3][m] = v.w;
    }
    __syncthreads();

    // XW: thread = output column e, computes 32 rows.
    const int e = tid;
    float acc[TM];
#pragma unroll
    for (int m = 0; m < TM; ++m) acc[m] = 0.f;
    const float* Wp = W + e;
#pragma unroll 2
    for (int d = 0; d < DD; ++d) {
        const float w = Wp[(size_t)d * DD];
#pragma unroll
        for (int m = 0; m < TM; m += 4) {
            const float4 a = *(const float4*)&As[d][m];
            acc[m + 0] = fmaf(a.x, w, acc[m + 0]);
            acc[m + 1] = fmaf(a.y, w, acc[m + 1]);
            acc[m + 2] = fmaf(a.z, w, acc[m + 2]);
            acc[m + 3] = fmaf(a.w, w, acc[m + 3]);
        }
    }
    float* o = g_xw + ((size_t)b * T + t0) * DD + e;
    for (int m = 0; m < rows; ++m) o[(size_t)m * DD] = acc[m];

    // GK tail: 32 rows x 8 slots = 256 dot products, one per thread.
    {
        const int m = tid >> 3, s = tid & 7;
        if (m < rows) {
            const float* kp = keys + s * DD;
            float v = 0.f;
#pragma unroll 4
            for (int d = 0; d < DD; ++d) v = fmaf(As[d][m], kp[d], v);
            g_gk[((size_t)b * T + t0 + m) * SS + s] = v;
        }
    }
}

// ---------------------------------------------------------------------------
// Recurrence: one CTA per batch, exactly len[b] steps. SMEM holds the RAW
// (pre-normalization) state h; the per-slot normalization scale r[s] lives in
// registers (identical in every thread) and is folded into the gate logit,
// the states@U result, and the states term. This makes the state write
// own-column-only, so each step needs just 2 barriers.
// ---------------------------------------------------------------------------
__global__ __launch_bounds__(256, 4) void dm_kernel(
    const float* __restrict__ inputs,
    const int*   __restrict__ lengths,
    const float* __restrict__ keys,
    const float* __restrict__ U,
    const float* __restrict__ gate_bias,
    float*       __restrict__ out,
    int T)
{
    const int b    = blockIdx.x;
    const int e    = threadIdx.x;
    const int lane = e & 31;
    const int warp = e >> 5;

    __shared__ __align__(16) float st[DD][SS];   // raw h, transposed [d][s]
    __shared__ __align__(16) float kvb[SS * DD];
    __shared__ __align__(16) float red1[SS][8];  // gate partials  [s][warp]
    __shared__ __align__(16) float red2[SS][8];  // norm partials  [s][warp]

#pragma unroll
    for (int s = 0; s < SS; ++s) {
        st[e][s]       = keys[s * DD + e];       // init state = keys (raw, r=1)
        kvb[s * DD + e] = g_kvb[s * DD + e];
    }
    const int   len   = lengths[b];
    const float gbias = gate_bias[0];
    const float* xb  = inputs + (size_t)b * T * DD + e;
    const float* xwb = g_xw   + (size_t)b * T * DD + e;
    const float* gkb = g_gk   + (size_t)b * T * SS;
    const float* Up  = U + e;

    float r[SS];
#pragma unroll
    for (int s = 0; s < SS; ++s) r[s] = 1.f;
    __syncthreads();

    float  xwv = xwb[0];
    float  xv  = xb[0];
    float4 gk0 = *(const float4*)&gkb[0];
    float4 gk1 = *(const float4*)&gkb[4];

    for (int t = 0; t < len; ++t) {
        // ---- phase A: gate partials (raw) + states@U GEMM (raw) ----
        const float4 s0 = *(const float4*)&st[e][0];
        const float4 s1 = *(const float4*)&st[e][4];
        float p[SS] = { xv * s0.x, xv * s0.y, xv * s0.z, xv * s0.w,
                        xv * s1.x, xv * s1.y, xv * s1.z, xv * s1.w };
#pragma unroll
        for (int s = 0; s < SS; ++s)
#pragma unroll
            for (int o = 16; o > 0; o >>= 1)
                p[s] += __shfl_xor_sync(0xffffffffu, p[s], o);
        if (lane == 0) {
#pragma unroll
            for (int s = 0; s < SS; ++s) red1[s][warp] = p[s];
        }

        // prefetch next step's t-dependent scalars during the GEMM
        const int   tn    = (t + 1 < len) ? t + 1 : t;
        const float xv_n  = xb [(size_t)tn * DD];
        const float xw_n  = xwb[(size_t)tn * DD];
        const float4 gk0n = *(const float4*)&gkb[(size_t)tn * SS];
        const float4 gk1n = *(const float4*)&gkb[(size_t)tn * SS + 4];

        float a0 = 0.f, a1 = 0.f, a2 = 0.f, a3 = 0.f;
        float a4 = 0.f, a5 = 0.f, a6 = 0.f, a7 = 0.f;
#pragma unroll 8
        for (int d = 0; d < DD; ++d) {
            const float u = Up[(size_t)d * DD];
            const float4 x0 = *(const float4*)&st[d][0];
            const float4 x1 = *(const float4*)&st[d][4];
            a0 = fmaf(x0.x, u, a0); a1 = fmaf(x0.y, u, a1);
            a2 = fmaf(x0.z, u, a2); a3 = fmaf(x0.w, u, a3);
            a4 = fmaf(x1.x, u, a4); a5 = fmaf(x1.y, u, a5);
            a6 = fmaf(x1.z, u, a6); a7 = fmaf(x1.w, u, a7);
        }
        __syncthreads();   // S1: red1 visible; all st reads complete

        // ---- phase B: gates, update, own-column state write, norm partials
        const float acc[SS] = {a0, a1, a2, a3, a4, a5, a6, a7};
        const float gk [SS] = {gk0.x, gk0.y, gk0.z, gk0.w,
                               gk1.x, gk1.y, gk1.z, gk1.w};
        const float sv [SS] = {s0.x, s0.y, s0.z, s0.w, s1.x, s1.y, s1.z, s1.w};
        float h[SS], q[SS];
#pragma unroll
        for (int s = 0; s < SS; ++s) {
            const float4 u0 = *(const float4*)&red1[s][0];
            const float4 u1 = *(const float4*)&red1[s][4];
            const float ls = ((u0.x + u0.y) + (u0.z + u0.w))
                           + ((u1.x + u1.y) + (u1.z + u1.w));
            const float logit = fmaf(r[s], ls, gk[s] + gbias);
            const float g = __fdividef(1.f, 1.f + __expf(-logit));
            const float pre = fmaf(r[s], acc[s], kvb[s * DD + e] + xwv);
            const float ht  = pre > 0.f ? pre : (__expf(pre) - 1.f);
            h[s] = fmaf(r[s], sv[s], g * ht);
            q[s] = h[s] * h[s];
        }
        *(float4*)&st[e][0] = make_float4(h[0], h[1], h[2], h[3]);
        *(float4*)&st[e][4] = make_float4(h[4], h[5], h[6], h[7]);
#pragma unroll
        for (int s = 0; s < SS; ++s)
#pragma unroll
            for (int o = 16; o > 0; o >>= 1)
                q[s] += __shfl_xor_sync(0xffffffffu, q[s], o);
        if (lane == 0) {
#pragma unroll
            for (int s = 0; s < SS; ++s) red2[s][warp] = q[s];
        }
        __syncthreads();   // S2: red2 + st writes visible

#pragma unroll
        for (int s = 0; s < SS; ++s) {
            const float4 u0 = *(const float4*)&red2[s][0];
            const float4 u1 = *(const float4*)&red2[s][4];
            const float n2 = ((u0.x + u0.y) + (u0.z + u0.w))
                           + ((u1.x + u1.y) + (u1.z + u1.w));
            r[s] = (n2 > 1e-24f) ? rsqrtf(n2) : 1e12f;  // 1/max(||h||,1e-12)
        }
        xv = xv_n; xwv = xw_n; gk0 = gk0n; gk1 = gk1n;
    }

    float* ob = out + (size_t)b * SS * DD + e;
#pragma unroll
    for (int s = 0; s < SS; ++s)
        ob[s * DD] = st[e][s] * r[s];
}

// ---------------------------------------------------------------------------
// Inputs: inputs, lengths, keys, U, V, W, gate_bias, state_bias. Out: [B,S,D].
// ---------------------------------------------------------------------------
extern "C" void kernel_launch(void* const* d_in, const int* in_sizes, int n_in,
                              void* d_out, int out_size) {
    const float* inputs     = (const float*)d_in[0];
    const int*   lengths    = (const int*)  d_in[1];
    const float* keys       = (const float*)d_in[2];
    const float* U          = (const float*)d_in[3];
    const float* V          = (const float*)d_in[4];
    const float* W          = (const float*)d_in[5];
    const float* gate_bias  = (const float*)d_in[6];
    const float* state_bias = (const float*)d_in[7];

    const int B = in_sizes[1];                 // lengths element count
    const int T = in_sizes[0] / (B * DD);      // inputs = B*T*D

    kvb_kernel<<<SS, DD>>>(keys, V, state_bias);
    xw_kernel<<<dim3((T + TM - 1) / TM, B), 256>>>(inputs, lengths, W, keys, T);
    dm_kernel<<<B, DD>>>(inputs, lengths, keys, U, gate_bias, (float*)d_out, T);
}

// round 3
// speedup vs baseline: 1.3623x; 1.0348x over previous
#include <cuda_runtime.h>
#include <math.h>

#define DD 256   // feature dim D
#define SS 8     // memory slots S
#define MAXB 512
#define MAXT 256
#define TM 32    // rows per XW tile

typedef unsigned long long u64;

// ---- packed fp32x2 helpers (Blackwell FFMA2; IEEE-identical to 2x fmaf) ----
__device__ __forceinline__ u64 pack2(float lo, float hi) {
    u64 r; asm("mov.b64 %0, {%1, %2};" : "=l"(r) : "f"(lo), "f"(hi)); return r;
}
__device__ __forceinline__ void fma2(u64& acc, u64 a, u64 b) {
    asm("fma.rn.f32x2 %0, %1, %2, %0;" : "+l"(acc) : "l"(a), "l"(b));
}
__device__ __forceinline__ float2 unpack2(u64 v) {
    float lo, hi; asm("mov.b64 {%0, %1}, %2;" : "=f"(lo), "=f"(hi) : "l"(v));
    return make_float2(lo, hi);
}

// Legal scratch: __device__ globals.
__device__ float g_kvb[SS * DD];                         // keys@V + state_bias
__device__ float g_xw[(size_t)MAXB * MAXT * DD];         // x@W     [B,T,D]
__device__ float g_gk[(size_t)MAXB * MAXT * SS];         // x@keys^T[B,T,S]

// ---------------------------------------------------------------------------
// kvb[s][e] = sum_d keys[s][d] * V[d][e] + state_bias[e]
// ---------------------------------------------------------------------------
__global__ void kvb_kernel(const float* __restrict__ keys,
                           const float* __restrict__ V,
                           const float* __restrict__ state_bias) {
    const int s = blockIdx.x;
    const int e = threadIdx.x;
    __shared__ float krow[DD];
    krow[e] = keys[s * DD + e];
    __syncthreads();
    float acc = state_bias[e];
#pragma unroll 4
    for (int d = 0; d < DD; ++d)
        acc = fmaf(krow[d], V[(size_t)d * DD + e], acc);
    g_kvb[s * DD + e] = acc;
}

// ---------------------------------------------------------------------------
// Precompute XW[b,t,:] = x@W and GK[b,t,:] = x@keys^T for t < len[b].
// f32x2-packed accumulators over row pairs (rows contiguous in As[d][.]).
// ---------------------------------------------------------------------------
__global__ __launch_bounds__(256) void xw_kernel(
    const float* __restrict__ inputs,   // [B,T,D]
    const int*   __restrict__ lengths,
    const float* __restrict__ W,        // [D,D]
    const float* __restrict__ keys,     // [S,D]
    int T)
{
    const int b  = blockIdx.y;
    const int t0 = blockIdx.x * TM;
    if (t0 >= lengths[b]) return;        // fully-masked tile: no work
    const int rows = min(TM, T - t0);

    __shared__ __align__(16) float As[DD][TM];   // transposed x-tile, 32KB
    const float* A = inputs + ((size_t)b * T + t0) * DD;
    const int tid = threadIdx.x;

    for (int i = tid; i < rows * (DD / 4); i += 256) {
        const int m = i / (DD / 4), d4 = i % (DD / 4);
        const float4 v = *(const float4*)&A[(size_t)m * DD + d4 * 4];
        As[d4 * 4 + 0][m] = v.x;
        As[d4 * 4 + 1][m] = v.y;
        As[d4 * 4 + 2][m] = v.z;
        As[d4 * 4 + 3][m] = v.w;
    }
    __syncthreads();

    const int e = tid;
    u64 acc2[TM / 2];
#pragma unroll
    for (int m = 0; m < TM / 2; ++m) acc2[m] = 0ull;
    const float* wp = W + e;
#pragma unroll 2
    for (int d = 0; d < DD; ++d) {
        const float w = *wp; wp += DD;
        const u64 ww = pack2(w, w);
        const ulonglong2* ap = (const ulonglong2*)&As[d][0];
#pragma unroll
        for (int m4 = 0; m4 < TM / 4; ++m4) {
            const ulonglong2 a = ap[m4];
            fma2(acc2[m4 * 2 + 0], a.x, ww);
            fma2(acc2[m4 * 2 + 1], a.y, ww);
        }
    }
    float* o = g_xw + ((size_t)b * T + t0) * DD + e;
    for (int m = 0; m < rows; ++m) {
        const float2 f = unpack2(acc2[m >> 1]);
        o[(size_t)m * DD] = (m & 1) ? f.y : f.x;
    }

    // GK tail: 32 rows x 8 slots = 256 dot products, one per thread.
    {
        const int m = tid >> 3, s = tid & 7;
        if (m < rows) {
            const float* kp = keys + s * DD;
            float v = 0.f;
#pragma unroll 4
            for (int d = 0; d < DD; ++d) v = fmaf(As[d][m], kp[d], v);
            g_gk[((size_t)b * T + t0 + m) * SS + s] = v;
        }
    }
}

// ---------------------------------------------------------------------------
// Recurrence: one CTA per batch, exactly len[b] steps. Raw (un-normalized)
// state h in SMEM; per-slot norm scale r[s] in registers, folded into gate
// logit / states@U result / states term -> 2 barriers per step. GEMM uses
// packed f32x2 FMA (4 FMA2 per d instead of 8 FFMA).
// ---------------------------------------------------------------------------
__global__ __launch_bounds__(256, 4) void dm_kernel(
    const float* __restrict__ inputs,
    const int*   __restrict__ lengths,
    const float* __restrict__ keys,
    const float* __restrict__ U,
    const float* __restrict__ gate_bias,
    float*       __restrict__ out,
    int T)
{
    const int b    = blockIdx.x;
    const int e    = threadIdx.x;
    const int lane = e & 31;
    const int warp = e >> 5;

    __shared__ __align__(16) float st[DD][SS];   // raw h, transposed [d][s]
    __shared__ __align__(16) float kvb[SS * DD];
    __shared__ __align__(16) float red1[SS][8];  // gate partials  [s][warp]
    __shared__ __align__(16) float red2[SS][8];  // norm partials  [s][warp]

#pragma unroll
    for (int s = 0; s < SS; ++s) {
        st[e][s]        = keys[s * DD + e];      // init state = keys (raw, r=1)
        kvb[s * DD + e] = g_kvb[s * DD + e];
    }
    const int   len   = lengths[b];
    const float gbias = gate_bias[0];
    const float* xb  = inputs + (size_t)b * T * DD + e;
    const float* xwb = g_xw   + (size_t)b * T * DD + e;
    const float* gkb = g_gk   + (size_t)b * T * SS;
    const float* Up  = U + e;

    float r[SS];
#pragma unroll
    for (int s = 0; s < SS; ++s) r[s] = 1.f;
    __syncthreads();

    float  xwv = xwb[0];
    float  xv  = xb[0];
    float4 gk0 = *(const float4*)&gkb[0];
    float4 gk1 = *(const float4*)&gkb[4];

    for (int t = 0; t < len; ++t) {
        // ---- phase A: gate partials (raw) + states@U GEMM (raw, f32x2) ----
        const float4 s0 = *(const float4*)&st[e][0];
        const float4 s1 = *(const float4*)&st[e][4];
        float p[SS] = { xv * s0.x, xv * s0.y, xv * s0.z, xv * s0.w,
                        xv * s1.x, xv * s1.y, xv * s1.z, xv * s1.w };
#pragma unroll
        for (int s = 0; s < SS; ++s)
#pragma unroll
            for (int o = 16; o > 0; o >>= 1)
                p[s] += __shfl_xor_sync(0xffffffffu, p[s], o);
        if (lane == 0) {
#pragma unroll
            for (int s = 0; s < SS; ++s) red1[s][warp] = p[s];
        }

        // prefetch next step's t-dependent scalars during the GEMM
        const int   tn    = (t + 1 < len) ? t + 1 : t;
        const float xv_n  = xb [(size_t)tn * DD];
        const float xw_n  = xwb[(size_t)tn * DD];
        const float4 gk0n = *(const float4*)&gkb[(size_t)tn * SS];
        const float4 gk1n = *(const float4*)&gkb[(size_t)tn * SS + 4];

        u64 A01 = 0ull, A23 = 0ull, A45 = 0ull, A67 = 0ull;
        {
            const float* up = Up;
#pragma unroll 8
            for (int d = 0; d < DD; ++d) {
                const float u = *up; up += DD;
                const u64 uu = pack2(u, u);
                const ulonglong2 r0 = *(const ulonglong2*)&st[d][0];
                const ulonglong2 r1 = *(const ulonglong2*)&st[d][4];
                fma2(A01, r0.x, uu);
                fma2(A23, r0.y, uu);
                fma2(A45, r1.x, uu);
                fma2(A67, r1.y, uu);
            }
        }
        __syncthreads();   // S1: red1 visible; all st reads complete

        // ---- phase B: gates, update, own-column state write, norm partials
        const float2 f01 = unpack2(A01), f23 = unpack2(A23);
        const float2 f45 = unpack2(A45), f67 = unpack2(A67);
        const float acc[SS] = {f01.x, f01.y, f23.x, f23.y,
                               f45.x, f45.y, f67.x, f67.y};
        const float gk [SS] = {gk0.x, gk0.y, gk0.z, gk0.w,
                               gk1.x, gk1.y, gk1.z, gk1.w};
        const float sv [SS] = {s0.x, s0.y, s0.z, s0.w, s1.x, s1.y, s1.z, s1.w};
        float h[SS], q[SS];
#pragma unroll
        for (int s = 0; s < SS; ++s) {
            const float4 u0 = *(const float4*)&red1[s][0];
            const float4 u1 = *(const float4*)&red1[s][4];
            const float ls = ((u0.x + u0.y) + (u0.z + u0.w))
                           + ((u1.x + u1.y) + (u1.z + u1.w));
            const float logit = fmaf(r[s], ls, gk[s] + gbias);
            const float g = __fdividef(1.f, 1.f + __expf(-logit));
            const float pre = fmaf(r[s], acc[s], kvb[s * DD + e] + xwv);
            const float ht  = pre > 0.f ? pre : (__expf(pre) - 1.f);
            h[s] = fmaf(r[s], sv[s], g * ht);
            q[s] = h[s] * h[s];
        }
        *(float4*)&st[e][0] = make_float4(h[0], h[1], h[2], h[3]);
        *(float4*)&st[e][4] = make_float4(h[4], h[5], h[6], h[7]);
#pragma unroll
        for (int s = 0; s < SS; ++s)
#pragma unroll
            for (int o = 16; o > 0; o >>= 1)
                q[s] += __shfl_xor_sync(0xffffffffu, q[s], o);
        if (lane == 0) {
#pragma unroll
            for (int s = 0; s < SS; ++s) red2[s][warp] = q[s];
        }
        __syncthreads();   // S2: red2 + st writes visible

#pragma unroll
        for (int s = 0; s < SS; ++s) {
            const float4 u0 = *(const float4*)&red2[s][0];
            const float4 u1 = *(const float4*)&red2[s][4];
            const float n2 = ((u0.x + u0.y) + (u0.z + u0.w))
                           + ((u1.x + u1.y) + (u1.z + u1.w));
            r[s] = (n2 > 1e-24f) ? rsqrtf(n2) : 1e12f;  // 1/max(||h||,1e-12)
        }
        xv = xv_n; xwv = xw_n; gk0 = gk0n; gk1 = gk1n;
    }

    float* ob = out + (size_t)b * SS * DD + e;
#pragma unroll
    for (int s = 0; s < SS; ++s)
        ob[s * DD] = st[e][s] * r[s];
}

// ---------------------------------------------------------------------------
// Inputs: inputs, lengths, keys, U, V, W, gate_bias, state_bias. Out: [B,S,D].
// ---------------------------------------------------------------------------
extern "C" void kernel_launch(void* const* d_in, const int* in_sizes, int n_in,
                              void* d_out, int out_size) {
    const float* inputs     = (const float*)d_in[0];
    const int*   lengths    = (const int*)  d_in[1];
    const float* keys       = (const float*)d_in[2];
    const float* U          = (const float*)d_in[3];
    const float* V          = (const float*)d_in[4];
    const float* W          = (const float*)d_in[5];
    const float* gate_bias  = (const float*)d_in[6];
    const float* state_bias = (const float*)d_in[7];

    const int B = in_sizes[1];                 // lengths element count
    const int T = in_sizes[0] / (B * DD);      // inputs = B*T*D

    kvb_kernel<<<SS, DD>>>(keys, V, state_bias);
    xw_kernel<<<dim3((T + TM - 1) / TM, B), 256>>>(inputs, lengths, W, keys, T);
    dm_kernel<<<B, DD>>>(inputs, lengths, keys, U, gate_bias, (float*)d_out, T);
}

// round 4
// speedup vs baseline: 1.3757x; 1.0099x over previous
#include <cuda_runtime.h>
#include <math.h>

#define DD 256   // feature dim D
#define SS 8     // memory slots S
#define MAXB 512
#define MAXT 256
#define TM 32    // rows per XW tile

typedef unsigned long long u64;

// ---- packed fp32x2 helpers (Blackwell; IEEE-identical to scalar fp32) ----
__device__ __forceinline__ u64 pack2(float lo, float hi) {
    u64 r; asm("mov.b64 %0, {%1, %2};" : "=l"(r) : "f"(lo), "f"(hi)); return r;
}
__device__ __forceinline__ void fma2(u64& acc, u64 a, u64 b) {
    asm("fma.rn.f32x2 %0, %1, %2, %0;" : "+l"(acc) : "l"(a), "l"(b));
}
__device__ __forceinline__ u64 add2(u64 a, u64 b) {
    u64 r; asm("add.rn.f32x2 %0, %1, %2;" : "=l"(r) : "l"(a), "l"(b)); return r;
}
__device__ __forceinline__ float2 unpack2(u64 v) {
    float lo, hi; asm("mov.b64 {%0, %1}, %2;" : "=f"(lo), "=f"(hi) : "l"(v));
    return make_float2(lo, hi);
}

// Legal scratch: __device__ globals.
__device__ float g_kvb[SS * DD];                         // keys@V + state_bias
__device__ float g_xw[(size_t)MAXB * MAXT * DD];         // x@W     [B,T,D]
__device__ float g_gk[(size_t)MAXB * MAXT * SS];         // x@keys^T[B,T,S]

// ---------------------------------------------------------------------------
// kvb[s][e] = sum_d keys[s][d] * V[d][e] + state_bias[e]
// ---------------------------------------------------------------------------
__global__ void kvb_kernel(const float* __restrict__ keys,
                           const float* __restrict__ V,
                           const float* __restrict__ state_bias) {
    const int s = blockIdx.x;
    const int e = threadIdx.x;
    __shared__ float krow[DD];
    krow[e] = keys[s * DD + e];
    __syncthreads();
    float acc = state_bias[e];
#pragma unroll 4
    for (int d = 0; d < DD; ++d)
        acc = fmaf(krow[d], V[(size_t)d * DD + e], acc);
    g_kvb[s * DD + e] = acc;
}

// ---------------------------------------------------------------------------
// Precompute XW[b,t,:] = x@W and GK[b,t,:] = x@keys^T for t < len[b].
// ---------------------------------------------------------------------------
__global__ __launch_bounds__(256) void xw_kernel(
    const float* __restrict__ inputs,   // [B,T,D]
    const int*   __restrict__ lengths,
    const float* __restrict__ W,        // [D,D]
    const float* __restrict__ keys,     // [S,D]
    int T)
{
    const int b  = blockIdx.y;
    const int t0 = blockIdx.x * TM;
    if (t0 >= lengths[b]) return;        // fully-masked tile: no work
    const int rows = min(TM, T - t0);

    __shared__ __align__(16) float As[DD][TM];   // transposed x-tile, 32KB
    const float* A = inputs + ((size_t)b * T + t0) * DD;
    const int tid = threadIdx.x;

    for (int i = tid; i < rows * (DD / 4); i += 256) {
        const int m = i / (DD / 4), d4 = i % (DD / 4);
        const float4 v = *(const float4*)&A[(size_t)m * DD + d4 * 4];
        As[d4 * 4 + 0][m] = v.x;
        As[d4 * 4 + 1][m] = v.y;
        As[d4 * 4 + 2][m] = v.z;
        As[d4 * 4 + 3][m] = v.w;
    }
    __syncthreads();

    const int e = tid;
    u64 acc2[TM / 2];
#pragma unroll
    for (int m = 0; m < TM / 2; ++m) acc2[m] = 0ull;
    const float* wp = W + e;
#pragma unroll 2
    for (int d = 0; d < DD; ++d) {
        const float w = *wp; wp += DD;
        const u64 ww = pack2(w, w);
        const ulonglong2* ap = (const ulonglong2*)&As[d][0];
#pragma unroll
        for (int m4 = 0; m4 < TM / 4; ++m4) {
            const ulonglong2 a = ap[m4];
            fma2(acc2[m4 * 2 + 0], a.x, ww);
            fma2(acc2[m4 * 2 + 1], a.y, ww);
        }
    }
    float* o = g_xw + ((size_t)b * T + t0) * DD + e;
    for (int m = 0; m < rows; ++m) {
        const float2 f = unpack2(acc2[m >> 1]);
        o[(size_t)m * DD] = (m & 1) ? f.y : f.x;
    }

    // GK tail: 32 rows x 8 slots = 256 dot products, one per thread.
    {
        const int m = tid >> 3, s = tid & 7;
        if (m < rows) {
            const float* kp = keys + s * DD;
            float v = 0.f;
#pragma unroll 4
            for (int d = 0; d < DD; ++d) v = fmaf(As[d][m], kp[d], v);
            g_gk[((size_t)b * T + t0 + m) * SS + s] = v;
        }
    }
}

// ---------------------------------------------------------------------------
// Recurrence: one CTA of 512 threads per batch. Thread = (column e, half).
// GEMM d-split: each half accumulates all 8 slots over its 128 d-rows
// (disjoint halves of U -> no duplicate LDG), merged via one 16B SMEM
// exchange under the existing S1 barrier. Phase B / reductions are
// slot-split: each thread owns 4 slots. Raw state + deferred norm scale r[]
// as before; still exactly 2 barriers per step.
// ---------------------------------------------------------------------------
__global__ __launch_bounds__(512, 3) void dm_kernel(
    const float* __restrict__ inputs,
    const int*   __restrict__ lengths,
    const float* __restrict__ keys,
    const float* __restrict__ U,
    const float* __restrict__ gate_bias,
    float*       __restrict__ out,
    int T)
{
    const int b    = blockIdx.x;
    const int tid  = threadIdx.x;
    const int e    = tid & (DD - 1);     // output column
    const int half = tid >> 8;           // d-range half
    const int lane = tid & 31;
    const int warp = tid >> 5;           // 0..15

    __shared__ __align__(16) float st[DD][SS];    // raw h, transposed [d][s]
    __shared__ __align__(16) float kvbT[DD][SS];  // kvb transposed [e][s]
    __shared__ __align__(16) u64   part[2][DD][2];// cross-half GEMM exchange
    __shared__ __align__(16) float red1[SS][8];   // gate partials [s][warp0-7]
    __shared__ __align__(16) float red2[SS][8];   // norm partials [s][warp&7]

    // init: half h fills slots 4h..4h+3 of its column
#pragma unroll
    for (int j = 0; j < 4; ++j) {
        const int s = half * 4 + j;
        st[e][s]   = keys[s * DD + e];            // init state = keys (r = 1)
        kvbT[e][s] = g_kvb[s * DD + e];
    }
    const int   len   = lengths[b];
    const float gbias = gate_bias[0];
    const float* xb  = inputs + (size_t)b * T * DD + e;   // used by half 0
    const float* xwb = g_xw   + (size_t)b * T * DD + e;
    const float* gkb = g_gk   + (size_t)b * T * SS + half * 4;
    const float* Up  = U + (size_t)(half * 128) * DD + e;

    float r[4] = {1.f, 1.f, 1.f, 1.f};
    __syncthreads();

    float  xv  = (half == 0) ? xb[0] : 0.f;
    float  xwv = xwb[0];
    float4 gk  = *(const float4*)&gkb[0];

    for (int t = 0; t < len; ++t) {
        // ---- phase A ----
        // gates (half 0 only): p[s] = x[e]*st[e][s], warp-reduced into red1
        if (half == 0) {
            const float4 s0 = *(const float4*)&st[e][0];
            const float4 s1 = *(const float4*)&st[e][4];
            float p[SS] = { xv * s0.x, xv * s0.y, xv * s0.z, xv * s0.w,
                            xv * s1.x, xv * s1.y, xv * s1.z, xv * s1.w };
#pragma unroll
            for (int s = 0; s < SS; ++s)
#pragma unroll
                for (int o = 16; o > 0; o >>= 1)
                    p[s] += __shfl_xor_sync(0xffffffffu, p[s], o);
            if (lane == 0) {
#pragma unroll
                for (int s = 0; s < SS; ++s) red1[s][warp] = p[s];
            }
        }

        // prefetch next step's scalars during the GEMM
        const int   tn   = (t + 1 < len) ? t + 1 : t;
        const float xv_n = (half == 0) ? xb[(size_t)tn * DD] : 0.f;
        const float xw_n = xwb[(size_t)tn * DD];
        const float4 gk_n = *(const float4*)&gkb[(size_t)tn * SS];

        // GEMM over own 128-row d-range, all 8 slots
        u64 A01 = 0ull, A23 = 0ull, A45 = 0ull, A67 = 0ull;
        {
            const float* up = Up;
            const int d0 = half * 128;
#pragma unroll 8
            for (int d = d0; d < d0 + 128; ++d) {
                const float u = *up; up += DD;
                const u64 uu = pack2(u, u);
                const ulonglong2 r0 = *(const ulonglong2*)&st[d][0];
                const ulonglong2 r1 = *(const ulonglong2*)&st[d][4];
                fma2(A01, r0.x, uu);
                fma2(A23, r0.y, uu);
                fma2(A45, r1.x, uu);
                fma2(A67, r1.y, uu);
            }
        }
        // exchange: each half ships the 2 pairs the OTHER half finalizes
        if (half == 0) { ulonglong2 v = {A45, A67}; *(ulonglong2*)&part[0][e][0] = v; }
        else           { ulonglong2 v = {A01, A23}; *(ulonglong2*)&part[1][e][0] = v; }
        __syncthreads();   // S1

        // ---- phase B: own 4 slots (s = 4*half + j) ----
        const ulonglong2 oth = *(const ulonglong2*)&part[1 - half][e][0];
        u64 P0, P1;        // slot pairs (4h+0,4h+1), (4h+2,4h+3)
        if (half == 0) { P0 = add2(A01, oth.x); P1 = add2(A23, oth.y); }
        else           { P0 = add2(A45, oth.x); P1 = add2(A67, oth.y); }
        const float2 f0 = unpack2(P0), f1 = unpack2(P1);
        const float acc[4] = {f0.x, f0.y, f1.x, f1.y};
        const float gkv[4] = {gk.x, gk.y, gk.z, gk.w};
        const float4 svv = *(const float4*)&st[e][half * 4];
        const float sv[4] = {svv.x, svv.y, svv.z, svv.w};
        const float4 kvv = *(const float4*)&kvbT[e][half * 4];
        const float kv[4] = {kvv.x, kvv.y, kvv.z, kvv.w};

        float h[4], q[4];
#pragma unroll
        for (int j = 0; j < 4; ++j) {
            const int s = half * 4 + j;
            const float4 u0 = *(const float4*)&red1[s][0];
            const float4 u1 = *(const float4*)&red1[s][4];
            const float ls = ((u0.x + u0.y) + (u0.z + u0.w))
                           + ((u1.x + u1.y) + (u1.z + u1.w));
            const float logit = fmaf(r[j], ls, gkv[j] + gbias);
            const float g = __fdividef(1.f, 1.f + __expf(-logit));
            const float pre = fmaf(r[j], acc[j], kv[j] + xwv);
            const float ht  = pre > 0.f ? pre : (__expf(pre) - 1.f);
            h[j] = fmaf(r[j], sv[j], g * ht);
            q[j] = h[j] * h[j];
        }
        *(float4*)&st[e][half * 4] = make_float4(h[0], h[1], h[2], h[3]);
#pragma unroll
        for (int j = 0; j < 4; ++j)
#pragma unroll
            for (int o = 16; o > 0; o >>= 1)
                q[j] += __shfl_xor_sync(0xffffffffu, q[j], o);
        if (lane == 0) {
#pragma unroll
            for (int j = 0; j < 4; ++j) red2[half * 4 + j][warp & 7] = q[j];
        }
        __syncthreads();   // S2

#pragma unroll
        for (int j = 0; j < 4; ++j) {
            const int s = half * 4 + j;
            const float4 u0 = *(const float4*)&red2[s][0];
            const float4 u1 = *(const float4*)&red2[s][4];
            const float n2 = ((u0.x + u0.y) + (u0.z + u0.w))
                           + ((u1.x + u1.y) + (u1.z + u1.w));
            r[j] = (n2 > 1e-24f) ? rsqrtf(n2) : 1e12f;  // 1/max(||h||,1e-12)
        }
        xv = xv_n; xwv = xw_n; gk = gk_n;
    }

    float* ob = out + (size_t)b * SS * DD + e;
#pragma unroll
    for (int j = 0; j < 4; ++j) {
        const int s = half * 4 + j;
        ob[(size_t)s * DD] = st[e][s] * r[j];
    }
}

// ---------------------------------------------------------------------------
// Inputs: inputs, lengths, keys, U, V, W, gate_bias, state_bias. Out: [B,S,D].
// ---------------------------------------------------------------------------
extern "C" void kernel_launch(void* const* d_in, const int* in_sizes, int n_in,
                              void* d_out, int out_size) {
    const float* inputs     = (const float*)d_in[0];
    const int*   lengths    = (const int*)  d_in[1];
    const float* keys       = (const float*)d_in[2];
    const float* U          = (const float*)d_in[3];
    const float* V          = (const float*)d_in[4];
    const float* W          = (const float*)d_in[5];
    const float* gate_bias  = (const float*)d_in[6];
    const float* state_bias = (const float*)d_in[7];

    const int B = in_sizes[1];                 // lengths element count
    const int T = in_sizes[0] / (B * DD);      // inputs = B*T*D

    kvb_kernel<<<SS, DD>>>(keys, V, state_bias);
    xw_kernel<<<dim3((T + TM - 1) / TM, B), 256>>>(inputs, lengths, W, keys, T);
    dm_kernel<<<B, 512>>>(inputs, lengths, keys, U, gate_bias, (float*)d_out, T);
}

// round 5
// speedup vs baseline: 1.6571x; 1.2045x over previous
#include <cuda_runtime.h>
#include <math.h>

#define DD 256   // feature dim D
#define SS 8     // memory slots S
#define MAXB 512
#define MAXT 256
#define TM 32    // rows per XW tile

typedef unsigned long long u64;

// ---- packed fp32x2 helpers (Blackwell; IEEE-identical to scalar fp32) ----
__device__ __forceinline__ u64 pack2(float lo, float hi) {
    u64 r; asm("mov.b64 %0, {%1, %2};" : "=l"(r) : "f"(lo), "f"(hi)); return r;
}
__device__ __forceinline__ void fma2(u64& acc, u64 a, u64 b) {
    asm("fma.rn.f32x2 %0, %1, %2, %0;" : "+l"(acc) : "l"(a), "l"(b));
}
__device__ __forceinline__ float2 unpack2(u64 v) {
    float lo, hi; asm("mov.b64 {%0, %1}, %2;" : "=f"(lo), "=f"(hi) : "l"(v));
    return make_float2(lo, hi);
}

// Legal scratch: __device__ globals.
__device__ float g_xw[(size_t)MAXB * MAXT * DD];         // x@W     [B,T,D]
__device__ float g_gk[(size_t)MAXB * MAXT * SS];         // x@keys^T[B,T,S]

// ---------------------------------------------------------------------------
// Precompute XW[b,t,:] = x@W and GK[b,t,:] = x@keys^T for t < len[b].
// ---------------------------------------------------------------------------
__global__ __launch_bounds__(256) void xw_kernel(
    const float* __restrict__ inputs,   // [B,T,D]
    const int*   __restrict__ lengths,
    const float* __restrict__ W,        // [D,D]
    const float* __restrict__ keys,     // [S,D]
    int T)
{
    const int b  = blockIdx.y;
    const int t0 = blockIdx.x * TM;
    if (t0 >= lengths[b]) return;        // fully-masked tile: no work
    const int rows = min(TM, T - t0);

    __shared__ __align__(16) float As[DD][TM];   // transposed x-tile, 32KB
    const float* A = inputs + ((size_t)b * T + t0) * DD;
    const int tid = threadIdx.x;

    for (int i = tid; i < rows * (DD / 4); i += 256) {
        const int m = i / (DD / 4), d4 = i % (DD / 4);
        const float4 v = *(const float4*)&A[(size_t)m * DD + d4 * 4];
        As[d4 * 4 + 0][m] = v.x;
        As[d4 * 4 + 1][m] = v.y;
        As[d4 * 4 + 2][m] = v.z;
        As[d4 * 4 + 3][m] = v.w;
    }
    __syncthreads();

    const int e = tid;
    u64 acc2[TM / 2];
#pragma unroll
    for (int m = 0; m < TM / 2; ++m) acc2[m] = 0ull;
    const float* wp = W + e;
#pragma unroll 2
    for (int d = 0; d < DD; ++d) {
        const float w = *wp; wp += DD;
        const u64 ww = pack2(w, w);
        const ulonglong2* ap = (const ulonglong2*)&As[d][0];
#pragma unroll
        for (int m4 = 0; m4 < TM / 4; ++m4) {
            const ulonglong2 a = ap[m4];
            fma2(acc2[m4 * 2 + 0], a.x, ww);
            fma2(acc2[m4 * 2 + 1], a.y, ww);
        }
    }
    float* o = g_xw + ((size_t)b * T + t0) * DD + e;
    for (int m = 0; m < rows; ++m) {
        const float2 f = unpack2(acc2[m >> 1]);
        o[(size_t)m * DD] = (m & 1) ? f.y : f.x;
    }

    // GK tail: 32 rows x 8 slots = 256 dot products, one per thread.
    {
        const int m = tid >> 3, s = tid & 7;
        if (m < rows) {
            const float* kp = keys + s * DD;
            float v = 0.f;
#pragma unroll 4
            for (int d = 0; d < DD; ++d) v = fmaf(As[d][m], kp[d], v);
            g_gk[((size_t)b * T + t0 + m) * SS + s] = v;
        }
    }
}

// ---------------------------------------------------------------------------
// Recurrence: one CTA of 256 threads per batch, len[b] steps. Raw state h in
// SMEM (transposed [d][s]); per-slot deferred norm scale r[s] in registers;
// kvb = keys@V + state_bias computed once per CTA at init, held in registers
// (own-column only). 2 barriers per step. Register budget 128 (no spills).
// ---------------------------------------------------------------------------
__global__ __launch_bounds__(256, 2) void dm_kernel(
    const float* __restrict__ inputs,
    const int*   __restrict__ lengths,
    const float* __restrict__ keys,
    const float* __restrict__ U,
    const float* __restrict__ V,
    const float* __restrict__ gate_bias,
    const float* __restrict__ state_bias,
    float*       __restrict__ out,
    int T)
{
    const int b    = blockIdx.x;
    const int e    = threadIdx.x;
    const int lane = e & 31;
    const int warp = e >> 5;

    __shared__ __align__(16) float st[DD][SS];   // raw h, transposed [d][s]
    __shared__ __align__(16) float red1[SS][8];  // gate partials  [s][warp]
    __shared__ __align__(16) float red2[SS][8];  // norm partials  [s][warp]

#pragma unroll
    for (int s = 0; s < SS; ++s)
        st[e][s] = keys[s * DD + e];             // init state = keys (raw, r=1)
    __syncthreads();

    // ---- kvb[e][s] = sum_d keys[s][d]*V[d][e] + sbias[e], in registers ----
    float kv[SS];
    {
        u64 K01 = 0ull, K23 = 0ull, K45 = 0ull, K67 = 0ull;
        const float* vp = V + e;
#pragma unroll 8
        for (int d = 0; d < DD; ++d) {
            const float v = *vp; vp += DD;
            const u64 vv = pack2(v, v);
            const ulonglong2 r0 = *(const ulonglong2*)&st[d][0];
            const ulonglong2 r1 = *(const ulonglong2*)&st[d][4];
            fma2(K01, r0.x, vv);
            fma2(K23, r0.y, vv);
            fma2(K45, r1.x, vv);
            fma2(K67, r1.y, vv);
        }
        const float sb = state_bias[e];
        const float2 k01 = unpack2(K01), k23 = unpack2(K23);
        const float2 k45 = unpack2(K45), k67 = unpack2(K67);
        kv[0] = k01.x + sb; kv[1] = k01.y + sb;
        kv[2] = k23.x + sb; kv[3] = k23.y + sb;
        kv[4] = k45.x + sb; kv[5] = k45.y + sb;
        kv[6] = k67.x + sb; kv[7] = k67.y + sb;
    }

    const int   len   = lengths[b];
    const float gbias = gate_bias[0];
    const float* xb  = inputs + (size_t)b * T * DD + e;
    const float* xwb = g_xw   + (size_t)b * T * DD + e;
    const float* gkb = g_gk   + (size_t)b * T * SS;
    const float* Up  = U + e;

    float r[SS];
#pragma unroll
    for (int s = 0; s < SS; ++s) r[s] = 1.f;

    float  xwv = xwb[0];
    float  xv  = xb[0];
    float4 gk0 = *(const float4*)&gkb[0];
    float4 gk1 = *(const float4*)&gkb[4];

    for (int t = 0; t < len; ++t) {
        // ---- phase A: gate partials (raw) + states@U GEMM (raw, f32x2) ----
        const float4 s0 = *(const float4*)&st[e][0];
        const float4 s1 = *(const float4*)&st[e][4];
        float p[SS] = { xv * s0.x, xv * s0.y, xv * s0.z, xv * s0.w,
                        xv * s1.x, xv * s1.y, xv * s1.z, xv * s1.w };
#pragma unroll
        for (int s = 0; s < SS; ++s)
#pragma unroll
            for (int o = 16; o > 0; o >>= 1)
                p[s] += __shfl_xor_sync(0xffffffffu, p[s], o);
        if (lane == 0) {
#pragma unroll
            for (int s = 0; s < SS; ++s) red1[s][warp] = p[s];
        }

        // prefetch next step's t-dependent scalars during the GEMM
        const int   tn    = (t + 1 < len) ? t + 1 : t;
        const float xv_n  = xb [(size_t)tn * DD];
        const float xw_n  = xwb[(size_t)tn * DD];
        const float4 gk0n = *(const float4*)&gkb[(size_t)tn * SS];
        const float4 gk1n = *(const float4*)&gkb[(size_t)tn * SS + 4];

        u64 A01 = 0ull, A23 = 0ull, A45 = 0ull, A67 = 0ull;
        {
            const float* up = Up;
#pragma unroll 8
            for (int d = 0; d < DD; ++d) {
                const float u = *up; up += DD;
                const u64 uu = pack2(u, u);
                const ulonglong2 r0 = *(const ulonglong2*)&st[d][0];
                const ulonglong2 r1 = *(const ulonglong2*)&st[d][4];
                fma2(A01, r0.x, uu);
                fma2(A23, r0.y, uu);
                fma2(A45, r1.x, uu);
                fma2(A67, r1.y, uu);
            }
        }
        __syncthreads();   // S1: red1 visible; all st reads complete

        // ---- phase B: gates, update, own-column state write, norm partials
        const float2 f01 = unpack2(A01), f23 = unpack2(A23);
        const float2 f45 = unpack2(A45), f67 = unpack2(A67);
        const float acc[SS] = {f01.x, f01.y, f23.x, f23.y,
                               f45.x, f45.y, f67.x, f67.y};
        const float gk [SS] = {gk0.x, gk0.y, gk0.z, gk0.w,
                               gk1.x, gk1.y, gk1.z, gk1.w};
        const float sv [SS] = {s0.x, s0.y, s0.z, s0.w, s1.x, s1.y, s1.z, s1.w};
        float h[SS], q[SS];
#pragma unroll
        for (int s = 0; s < SS; ++s) {
            const float4 u0 = *(const float4*)&red1[s][0];
            const float4 u1 = *(const float4*)&red1[s][4];
            const float ls = ((u0.x + u0.y) + (u0.z + u0.w))
                           + ((u1.x + u1.y) + (u1.z + u1.w));
            const float logit = fmaf(r[s], ls, gk[s] + gbias);
            const float g = __fdividef(1.f, 1.f + __expf(-logit));
            const float pre = fmaf(r[s], acc[s], kv[s] + xwv);
            const float ht  = pre > 0.f ? pre : (__expf(pre) - 1.f);
            h[s] = fmaf(r[s], sv[s], g * ht);
            q[s] = h[s] * h[s];
        }
        *(float4*)&st[e][0] = make_float4(h[0], h[1], h[2], h[3]);
        *(float4*)&st[e][4] = make_float4(h[4], h[5], h[6], h[7]);
#pragma unroll
        for (int s = 0; s < SS; ++s)
#pragma unroll
            for (int o = 16; o > 0; o >>= 1)
                q[s] += __shfl_xor_sync(0xffffffffu, q[s], o);
        if (lane == 0) {
#pragma unroll
            for (int s = 0; s < SS; ++s) red2[s][warp] = q[s];
        }
        __syncthreads();   // S2: red2 + st writes visible

#pragma unroll
        for (int s = 0; s < SS; ++s) {
            const float4 u0 = *(const float4*)&red2[s][0];
            const float4 u1 = *(const float4*)&red2[s][4];
            const float n2 = ((u0.x + u0.y) + (u0.z + u0.w))
                           + ((u1.x + u1.y) + (u1.z + u1.w));
            r[s] = (n2 > 1e-24f) ? rsqrtf(n2) : 1e12f;  // 1/max(||h||,1e-12)
        }
        xv = xv_n; xwv = xw_n; gk0 = gk0n; gk1 = gk1n;
    }

    float* ob = out + (size_t)b * SS * DD + e;
#pragma unroll
    for (int s = 0; s < SS; ++s)
        ob[s * DD] = st[e][s] * r[s];
}

// ---------------------------------------------------------------------------
// Inputs: inputs, lengths, keys, U, V, W, gate_bias, state_bias. Out: [B,S,D].
// ---------------------------------------------------------------------------
extern "C" void kernel_launch(void* const* d_in, const int* in_sizes, int n_in,
                              void* d_out, int out_size) {
    const float* inputs     = (const float*)d_in[0];
    const int*   lengths    = (const int*)  d_in[1];
    const float* keys       = (const float*)d_in[2];
    const float* U          = (const float*)d_in[3];
    const float* V          = (const float*)d_in[4];
    const float* W          = (const float*)d_in[5];
    const float* gate_bias  = (const float*)d_in[6];
    const float* state_bias = (const float*)d_in[7];

    const int B = in_sizes[1];                 // lengths element count
    const int T = in_sizes[0] / (B * DD);      // inputs = B*T*D

    xw_kernel<<<dim3((T + TM - 1) / TM, B), 256>>>(inputs, lengths, W, keys, T);
    dm_kernel<<<B, DD>>>(inputs, lengths, keys, U, V, gate_bias, state_bias,
                         (float*)d_out, T);
}